// round 11
// baseline (speedup 1.0000x reference)
#include <cuda_runtime.h>
#include <cuda_fp16.h>
#include <stdint.h>
#include <math.h>

// ---------------- problem constants ----------------
#define MM      32768
#define TOPK    2
#define NH      2048
#define NF      4096
#define NE      8
#define NA      (MM*TOPK)
#define TILE_M  128
#define MAX_TILES 521
#define CAP     (MAX_TILES*TILE_M)     // 66688 padded rows

// ---------------- device scratch (R5-proven footprint: ~547MB) ----------------
__device__ int    g_counts[NE];
__device__ int    g_cursor[NE];
__device__ int    g_off[NE+1];
__device__ int    g_row_ids[CAP];
__device__ __align__(16) __half g_h[(size_t)CAP * (size_t)NF];   // fp16 intermediate

// ---------------- mma.sync m16n8k16 (fp16 in, fp32 acc) ----------------
#define MMA(c,a,b) \
    asm volatile("mma.sync.aligned.m16n8k16.row.col.f32.f16.f16.f32 " \
        "{%0,%1,%2,%3}, {%4,%5,%6,%7}, {%8,%9}, {%0,%1,%2,%3};" \
        : "+f"((c)[0]),"+f"((c)[1]),"+f"((c)[2]),"+f"((c)[3]) \
        : "r"((a)[0]),"r"((a)[1]),"r"((a)[2]),"r"((a)[3]),"r"((b)[0]),"r"((b)[1]))

__device__ __forceinline__ uint32_t pack2f(float lo, float hi) {
    __half2 h = __floats2half2_rn(lo, hi);
    return *(uint32_t*)&h;
}

// A smem: [m=128][k=16] halfs, row stride 24 halfs (48B).
// a-frag LDS word addr = r*12 + qi; lanes (g 0..7, qi 0..3): 12g+qi distinct mod 32. ✓
#define ASTR 24
// B smem: pre-paired uint32 Bp[kp=8][n=128], row stride 136 words.
// b-frag word addr = qi*136 + col -> (8qi + g) mod 32 all distinct. ✓
#define BPSTR 136

// ---------------- setup kernels (verbatim, proven) ----------------
__global__ void k_zero() {
    int t = threadIdx.x;
    if (t < NE) { g_counts[t] = 0; g_cursor[t] = 0; }
}
__global__ void k_count_fill(const int* __restrict__ topks) {
    __shared__ int h[NE];
    int t = threadIdx.x;
    if (t < NE) h[t] = 0;
    __syncthreads();
    int stride = gridDim.x * blockDim.x;
    int i = blockIdx.x * blockDim.x + t;
    for (int p = i; p < CAP; p += stride) g_row_ids[p] = -1;
    for (int p = i; p < NA; p += stride) atomicAdd(&h[topks[p]], 1);
    __syncthreads();
    if (t < NE && h[t]) atomicAdd(&g_counts[t], h[t]);
}
__global__ void k_offsets() {
    int s = 0; g_off[0] = 0;
    for (int e = 0; e < NE; e++) {
        s += (g_counts[e] + (TILE_M - 1)) & ~(TILE_M - 1);
        g_off[e + 1] = s;
    }
}
__global__ void k_scatter(const int* __restrict__ topks) {
    int stride = gridDim.x * blockDim.x;
    int i = blockIdx.x * blockDim.x + threadIdx.x;
    for (int p = i; p < NA; p += stride) {
        int e = topks[p];
        int pos = g_off[e] + atomicAdd(&g_cursor[e], 1);
        g_row_ids[pos] = p;
    }
}

// ---------------- GEMM A: h = silu(x@w1) * (x@w3) ----------------
// CTA 128M x 128N, K-step 16. 8 warps: wm=wid&1 (64 rows), wn=wid>>1 (32 cols).
// Grid (ct=32, rt=521): ct-fastest -> wave shares x rows, weight slab L2-resident.
__global__ __launch_bounds__(256, 1)
void gA(const float* __restrict__ x,
        const float* __restrict__ w1,
        const float* __restrict__ w3)
{
    __shared__ __half   Asm[2][TILE_M * ASTR];   // 12288 B
    __shared__ uint32_t B1p[2][8 * BPSTR];       //  8704 B
    __shared__ uint32_t B3p[2][8 * BPSTR];       //  8704 B
    __shared__ int      tok[TILE_M];

    int tid = threadIdx.x, lane = tid & 31, wid = tid >> 5;
    int wm = wid & 1, wn = wid >> 1;
    int g = lane >> 2, qi = lane & 3;
    int ct = blockIdx.x, rt = blockIdx.y;
    int rowstart = rt * TILE_M;
    if (rowstart >= g_off[NE]) return;
    int e = 0;
    while (e < NE - 1 && rowstart >= g_off[e + 1]) e++;
    int n0 = ct * 128;

    if (tid < TILE_M) {
        int f = g_row_ids[rowstart + tid];
        tok[tid] = (f < 0) ? 0 : (f >> 1);
    }
    __syncthreads();

    const float* w1e = w1 + (size_t)e * NH * NF + n0;
    const float* w3e = w3 + (size_t)e * NH * NF + n0;

    float accg[4][4][4], accu[4][4][4];
#pragma unroll
    for (int i = 0; i < 4; i++)
#pragma unroll
        for (int j = 0; j < 4; j++)
#pragma unroll
            for (int q = 0; q < 4; q++) { accg[i][j][q] = 0.f; accu[i][j][q] = 0.f; }

    // prefetch regs: A 2 float4; B: per matrix rows 2r,2r+1 (float4 each)
    float4 pa0, pa1, p10, p11, p30, p31;
    const int ar0 = tid >> 2,         ak0 = (tid & 3) * 4;
    const int ar1 = (tid + 256) >> 2, ak1 = ((tid + 256) & 3) * 4;
    const int bkp = tid >> 5;                 // kp row 0..7
    const int bc4 = (lane) * 4;               // col group 0..124

    auto LDGr = [&](int kt) {
        int k0 = kt * 16;
        pa0 = *(const float4*)(x + (size_t)tok[ar0] * NH + k0 + ak0);
        pa1 = *(const float4*)(x + (size_t)tok[ar1] * NH + k0 + ak1);
        p10 = *(const float4*)(w1e + (size_t)(k0 + 2 * bkp)     * NF + bc4);
        p11 = *(const float4*)(w1e + (size_t)(k0 + 2 * bkp + 1) * NF + bc4);
        p30 = *(const float4*)(w3e + (size_t)(k0 + 2 * bkp)     * NF + bc4);
        p31 = *(const float4*)(w3e + (size_t)(k0 + 2 * bkp + 1) * NF + bc4);
    };
    auto STSb = [&](int buf) {
        __half2 a0 = __floats2half2_rn(pa0.x, pa0.y), a1 = __floats2half2_rn(pa0.z, pa0.w);
        *(uint2*)&Asm[buf][ar0 * ASTR + ak0] = make_uint2(*(uint32_t*)&a0, *(uint32_t*)&a1);
        __half2 a2 = __floats2half2_rn(pa1.x, pa1.y), a3 = __floats2half2_rn(pa1.z, pa1.w);
        *(uint2*)&Asm[buf][ar1 * ASTR + ak1] = make_uint2(*(uint32_t*)&a2, *(uint32_t*)&a3);
        uint4 q1 = make_uint4(pack2f(p10.x, p11.x), pack2f(p10.y, p11.y),
                              pack2f(p10.z, p11.z), pack2f(p10.w, p11.w));
        *(uint4*)&B1p[buf][bkp * BPSTR + bc4] = q1;
        uint4 q3 = make_uint4(pack2f(p30.x, p31.x), pack2f(p30.y, p31.y),
                              pack2f(p30.z, p31.z), pack2f(p30.w, p31.w));
        *(uint4*)&B3p[buf][bkp * BPSTR + bc4] = q3;
    };

    LDGr(0); STSb(0); __syncthreads();
    const int KT = NH / 16;   // 128
    for (int kt = 0; kt < KT; kt++) {
        if (kt + 1 < KT) LDGr(kt + 1);
        int buf = kt & 1;
        uint32_t a[4][4];
#pragma unroll
        for (int mt = 0; mt < 4; mt++) {
            int r = wm * 64 + mt * 16 + g;
            a[mt][0] = *(const uint32_t*)&Asm[buf][ r      * ASTR + 2 * qi];
            a[mt][1] = *(const uint32_t*)&Asm[buf][(r + 8) * ASTR + 2 * qi];
            a[mt][2] = *(const uint32_t*)&Asm[buf][ r      * ASTR + 8 + 2 * qi];
            a[mt][3] = *(const uint32_t*)&Asm[buf][(r + 8) * ASTR + 8 + 2 * qi];
        }
#pragma unroll
        for (int nn = 0; nn < 4; nn++) {
            int col = wn * 32 + nn * 8 + g;
            uint32_t b1[2], b3[2];
            b1[0] = B1p[buf][ qi      * BPSTR + col];
            b1[1] = B1p[buf][(qi + 4) * BPSTR + col];
            b3[0] = B3p[buf][ qi      * BPSTR + col];
            b3[1] = B3p[buf][(qi + 4) * BPSTR + col];
#pragma unroll
            for (int mt = 0; mt < 4; mt++) {
                MMA(accg[mt][nn], a[mt], b1);
                MMA(accu[mt][nn], a[mt], b3);
            }
        }
        if (kt + 1 < KT) { STSb(buf ^ 1); __syncthreads(); }
    }

    // epilogue: silu(g)*u -> fp16 h
    int colbase = n0 + wn * 32 + qi * 2;
#pragma unroll
    for (int mt = 0; mt < 4; mt++)
#pragma unroll
        for (int rs = 0; rs < 2; rs++) {
            int row = rowstart + wm * 64 + mt * 16 + g + rs * 8;
            __half* dst = g_h + (size_t)row * NF + colbase;
#pragma unroll
            for (int nn = 0; nn < 4; nn++) {
                float g0 = accg[mt][nn][rs * 2],     u0 = accu[mt][nn][rs * 2];
                float g1 = accg[mt][nn][rs * 2 + 1], u1 = accu[mt][nn][rs * 2 + 1];
                float s0 = g0 / (1.f + __expf(-g0)) * u0;
                float s1 = g1 / (1.f + __expf(-g1)) * u1;
                *(__half2*)(dst + nn * 8) = __floats2half2_rn(s0, s1);
            }
        }
}

// ---------------- GEMM B: out = h @ w2 ----------------
__global__ __launch_bounds__(256, 2)
void gB(const float* __restrict__ w2, float* __restrict__ out)
{
    __shared__ __half   Asm2[2][TILE_M * ASTR];  // 12288 B
    __shared__ uint32_t B2p [2][8 * BPSTR];      //  8704 B

    int tid = threadIdx.x, lane = tid & 31, wid = tid >> 5;
    int wm = wid & 1, wn = wid >> 1;
    int g = lane >> 2, qi = lane & 3;
    int ct = blockIdx.x, rt = blockIdx.y;
    int rowstart = rt * TILE_M;
    if (rowstart >= g_off[NE]) return;
    int e = 0;
    while (e < NE - 1 && rowstart >= g_off[e + 1]) e++;
    int n0 = ct * 128;

    const __half* Ab  = g_h + (size_t)rowstart * NF;
    const float*  w2e = w2 + (size_t)e * NF * NH + n0;

    float acc[4][4][4];
#pragma unroll
    for (int i = 0; i < 4; i++)
#pragma unroll
        for (int j = 0; j < 4; j++)
#pragma unroll
            for (int q = 0; q < 4; q++) acc[i][j][q] = 0.f;

    uint4  pa;
    float4 pb0, pb1;
    const int aro = tid >> 1, aqo = (tid & 1) * 8;
    const int bkp = tid >> 5, bc4 = lane * 4;

    auto LDGr = [&](int kt) {
        int k0 = kt * 16;
        pa  = *(const uint4*) (Ab  + (size_t)aro * NF + k0 + aqo);
        pb0 = *(const float4*)(w2e + (size_t)(k0 + 2 * bkp)     * NH + bc4);
        pb1 = *(const float4*)(w2e + (size_t)(k0 + 2 * bkp + 1) * NH + bc4);
    };
    auto STSb = [&](int buf) {
        *(uint4*)&Asm2[buf][aro * ASTR + aqo] = pa;
        uint4 q = make_uint4(pack2f(pb0.x, pb1.x), pack2f(pb0.y, pb1.y),
                             pack2f(pb0.z, pb1.z), pack2f(pb0.w, pb1.w));
        *(uint4*)&B2p[buf][bkp * BPSTR + bc4] = q;
    };

    LDGr(0); STSb(0); __syncthreads();
    const int KT = NF / 16;   // 256
    for (int kt = 0; kt < KT; kt++) {
        if (kt + 1 < KT) LDGr(kt + 1);
        int buf = kt & 1;
        uint32_t a[4][4];
#pragma unroll
        for (int mt = 0; mt < 4; mt++) {
            int r = wm * 64 + mt * 16 + g;
            a[mt][0] = *(const uint32_t*)&Asm2[buf][ r      * ASTR + 2 * qi];
            a[mt][1] = *(const uint32_t*)&Asm2[buf][(r + 8) * ASTR + 2 * qi];
            a[mt][2] = *(const uint32_t*)&Asm2[buf][ r      * ASTR + 8 + 2 * qi];
            a[mt][3] = *(const uint32_t*)&Asm2[buf][(r + 8) * ASTR + 8 + 2 * qi];
        }
#pragma unroll
        for (int nn = 0; nn < 4; nn++) {
            int col = wn * 32 + nn * 8 + g;
            uint32_t b[2];
            b[0] = B2p[buf][ qi      * BPSTR + col];
            b[1] = B2p[buf][(qi + 4) * BPSTR + col];
#pragma unroll
            for (int mt = 0; mt < 4; mt++) MMA(acc[mt][nn], a[mt], b);
        }
        if (kt + 1 < KT) { STSb(buf ^ 1); __syncthreads(); }
    }

    int colbase = n0 + wn * 32 + qi * 2;
#pragma unroll
    for (int mt = 0; mt < 4; mt++)
#pragma unroll
        for (int rs = 0; rs < 2; rs++) {
            int lrow = wm * 64 + mt * 16 + g + rs * 8;
            int f = g_row_ids[rowstart + lrow];
            if (f < 0) continue;
            float* dst = out + (size_t)f * NH + colbase;
#pragma unroll
            for (int nn = 0; nn < 4; nn++) {
                float2 v = make_float2(acc[mt][nn][rs * 2], acc[mt][nn][rs * 2 + 1]);
                *(float2*)(dst + nn * 8) = v;
            }
        }
}

// ---------------- launch ----------------
extern "C" void kernel_launch(void* const* d_in, const int* in_sizes, int n_in,
                              void* d_out, int out_size)
{
    const float* x     = (const float*)d_in[0];
    const int*   topks = (const int*)  d_in[1];
    const float* w1    = (const float*)d_in[2];
    const float* w2    = (const float*)d_in[3];
    const float* w3    = (const float*)d_in[4];
    float* out = (float*)d_out;

    k_zero      <<<1, 32>>>();
    k_count_fill<<<256, 256>>>(topks);
    k_offsets   <<<1, 1>>>();
    k_scatter   <<<256, 256>>>(topks);
    gA<<<dim3(32, MAX_TILES), 256>>>(x, w1, w3);
    gB<<<dim3(16, MAX_TILES), 256>>>(w2, out);
}

// round 14
// speedup vs baseline: 1.2904x; 1.2904x over previous
#include <cuda_runtime.h>
#include <cuda_fp16.h>
#include <stdint.h>
#include <math.h>

// ---------------- problem constants ----------------
#define MM      32768
#define TOPK    2
#define NH      2048
#define NF      4096
#define NE      8
#define NA      (MM*TOPK)
#define TILE_M  128
#define MAX_TILES 521
#define CAP     (MAX_TILES*TILE_M)     // 66688 padded rows

// ---------------- device scratch (proven footprint) ----------------
__device__ int    g_counts[NE];
__device__ int    g_cursor[NE];
__device__ int    g_off[NE+1];
__device__ int    g_row_ids[CAP];
__device__ __align__(16) __half g_h[(size_t)CAP * (size_t)NF];   // fp16 intermediate

// ---------------- mma.sync m16n8k16 (fp16 in, fp32 acc) ----------------
#define MMA(c,a,b) \
    asm volatile("mma.sync.aligned.m16n8k16.row.col.f32.f16.f16.f32 " \
        "{%0,%1,%2,%3}, {%4,%5,%6,%7}, {%8,%9}, {%0,%1,%2,%3};" \
        : "+f"((c)[0]),"+f"((c)[1]),"+f"((c)[2]),"+f"((c)[3]) \
        : "r"((a)[0]),"r"((a)[1]),"r"((a)[2]),"r"((a)[3]),"r"((b)[0]),"r"((b)[1]))

__device__ __forceinline__ uint32_t pack2f(float lo, float hi) {
    __half2 h = __floats2half2_rn(lo, hi);
    return *(uint32_t*)&h;
}

// A smem: [m=128][k=16] halfs, row stride 24 halfs (48B); a-frag LDS conflict-free.
#define ASTR 24
// B smem: pre-paired uint32 Bp[kp=8][n=128], row stride 136 words;
// b-frag word addr (136qi + col) -> (8qi + g) mod 32 distinct: conflict-free.
#define BPSTR 136

// ---------------- setup kernels (verbatim, proven) ----------------
__global__ void k_zero() {
    int t = threadIdx.x;
    if (t < NE) { g_counts[t] = 0; g_cursor[t] = 0; }
}
__global__ void k_count_fill(const int* __restrict__ topks) {
    __shared__ int h[NE];
    int t = threadIdx.x;
    if (t < NE) h[t] = 0;
    __syncthreads();
    int stride = gridDim.x * blockDim.x;
    int i = blockIdx.x * blockDim.x + t;
    for (int p = i; p < CAP; p += stride) g_row_ids[p] = -1;
    for (int p = i; p < NA; p += stride) atomicAdd(&h[topks[p]], 1);
    __syncthreads();
    if (t < NE && h[t]) atomicAdd(&g_counts[t], h[t]);
}
__global__ void k_offsets() {
    int s = 0; g_off[0] = 0;
    for (int e = 0; e < NE; e++) {
        s += (g_counts[e] + (TILE_M - 1)) & ~(TILE_M - 1);
        g_off[e + 1] = s;
    }
}
__global__ void k_scatter(const int* __restrict__ topks) {
    int stride = gridDim.x * blockDim.x;
    int i = blockIdx.x * blockDim.x + threadIdx.x;
    for (int p = i; p < NA; p += stride) {
        int e = topks[p];
        int pos = g_off[e] + atomicAdd(&g_cursor[e], 1);
        g_row_ids[pos] = p;
    }
}

// ---------------- GEMM A: h = silu(x@w1) * (x@w3) ----------------
// CTA 128M x 128N, K-step 16. Grid (rt=521, ct=32) rt-fastest (R9 proven).
__global__ __launch_bounds__(256, 1)
void gA(const float* __restrict__ x,
        const float* __restrict__ w1,
        const float* __restrict__ w3)
{
    __shared__ __half   Asm[2][TILE_M * ASTR];   // 12288 B
    __shared__ uint32_t B1p[2][8 * BPSTR];       //  8704 B
    __shared__ uint32_t B3p[2][8 * BPSTR];       //  8704 B
    __shared__ int      tok[TILE_M];

    int tid = threadIdx.x, lane = tid & 31, wid = tid >> 5;
    int wm = wid & 1, wn = wid >> 1;
    int g = lane >> 2, qi = lane & 3;
    int rt = blockIdx.x, ct = blockIdx.y;        // rt-fastest (R9 orientation)
    int rowstart = rt * TILE_M;
    if (rowstart >= g_off[NE]) return;
    int e = 0;
    while (e < NE - 1 && rowstart >= g_off[e + 1]) e++;
    int n0 = ct * 128;

    if (tid < TILE_M) {
        int f = g_row_ids[rowstart + tid];
        tok[tid] = (f < 0) ? 0 : (f >> 1);
    }
    __syncthreads();

    const float* w1e = w1 + (size_t)e * NH * NF + n0;
    const float* w3e = w3 + (size_t)e * NH * NF + n0;

    float accg[4][4][4], accu[4][4][4];
#pragma unroll
    for (int i = 0; i < 4; i++)
#pragma unroll
        for (int j = 0; j < 4; j++)
#pragma unroll
            for (int q = 0; q < 4; q++) { accg[i][j][q] = 0.f; accu[i][j][q] = 0.f; }

    float4 pa0, pa1, p10, p11, p30, p31;
    const int ar0 = tid >> 2,         ak0 = (tid & 3) * 4;
    const int ar1 = (tid + 256) >> 2, ak1 = ((tid + 256) & 3) * 4;
    const int bkp = tid >> 5;                 // kp row 0..7 (pairs of k)
    const int bc4 = lane * 4;                 // col group

    auto LDGr = [&](int kt) {
        int k0 = kt * 16;
        pa0 = *(const float4*)(x + (size_t)tok[ar0] * NH + k0 + ak0);
        pa1 = *(const float4*)(x + (size_t)tok[ar1] * NH + k0 + ak1);
        p10 = *(const float4*)(w1e + (size_t)(k0 + 2 * bkp)     * NF + bc4);
        p11 = *(const float4*)(w1e + (size_t)(k0 + 2 * bkp + 1) * NF + bc4);
        p30 = *(const float4*)(w3e + (size_t)(k0 + 2 * bkp)     * NF + bc4);
        p31 = *(const float4*)(w3e + (size_t)(k0 + 2 * bkp + 1) * NF + bc4);
    };
    auto STSb = [&](int buf) {
        __half2 a0 = __floats2half2_rn(pa0.x, pa0.y), a1 = __floats2half2_rn(pa0.z, pa0.w);
        *(uint2*)&Asm[buf][ar0 * ASTR + ak0] = make_uint2(*(uint32_t*)&a0, *(uint32_t*)&a1);
        __half2 a2 = __floats2half2_rn(pa1.x, pa1.y), a3 = __floats2half2_rn(pa1.z, pa1.w);
        *(uint2*)&Asm[buf][ar1 * ASTR + ak1] = make_uint2(*(uint32_t*)&a2, *(uint32_t*)&a3);
        uint4 q1 = make_uint4(pack2f(p10.x, p11.x), pack2f(p10.y, p11.y),
                              pack2f(p10.z, p11.z), pack2f(p10.w, p11.w));
        *(uint4*)&B1p[buf][bkp * BPSTR + bc4] = q1;
        uint4 q3 = make_uint4(pack2f(p30.x, p31.x), pack2f(p30.y, p31.y),
                              pack2f(p30.z, p31.z), pack2f(p30.w, p31.w));
        *(uint4*)&B3p[buf][bkp * BPSTR + bc4] = q3;
    };

    LDGr(0); STSb(0); __syncthreads();
    const int KT = NH / 16;   // 128
    for (int kt = 0; kt < KT; kt++) {
        if (kt + 1 < KT) LDGr(kt + 1);
        int buf = kt & 1;
        uint32_t a[4][4];
#pragma unroll
        for (int mt = 0; mt < 4; mt++) {
            int r = wm * 64 + mt * 16 + g;
            a[mt][0] = *(const uint32_t*)&Asm[buf][ r      * ASTR + 2 * qi];
            a[mt][1] = *(const uint32_t*)&Asm[buf][(r + 8) * ASTR + 2 * qi];
            a[mt][2] = *(const uint32_t*)&Asm[buf][ r      * ASTR + 8 + 2 * qi];
            a[mt][3] = *(const uint32_t*)&Asm[buf][(r + 8) * ASTR + 8 + 2 * qi];
        }
#pragma unroll
        for (int nn = 0; nn < 4; nn++) {
            int col = wn * 32 + nn * 8 + g;
            uint32_t b1[2], b3[2];
            b1[0] = B1p[buf][ qi      * BPSTR + col];
            b1[1] = B1p[buf][(qi + 4) * BPSTR + col];
            b3[0] = B3p[buf][ qi      * BPSTR + col];
            b3[1] = B3p[buf][(qi + 4) * BPSTR + col];
#pragma unroll
            for (int mt = 0; mt < 4; mt++) {
                MMA(accg[mt][nn], a[mt], b1);
                MMA(accu[mt][nn], a[mt], b3);
            }
        }
        if (kt + 1 < KT) { STSb(buf ^ 1); __syncthreads(); }
    }

    // epilogue: silu(g)*u -> fp16 h
    int colbase = n0 + wn * 32 + qi * 2;
#pragma unroll
    for (int mt = 0; mt < 4; mt++)
#pragma unroll
        for (int rs = 0; rs < 2; rs++) {
            int row = rowstart + wm * 64 + mt * 16 + g + rs * 8;
            __half* dst = g_h + (size_t)row * NF + colbase;
#pragma unroll
            for (int nn = 0; nn < 4; nn++) {
                float g0 = accg[mt][nn][rs * 2],     u0 = accu[mt][nn][rs * 2];
                float g1 = accg[mt][nn][rs * 2 + 1], u1 = accu[mt][nn][rs * 2 + 1];
                float s0 = g0 / (1.f + __expf(-g0)) * u0;
                float s1 = g1 / (1.f + __expf(-g1)) * u1;
                *(__half2*)(dst + nn * 8) = __floats2half2_rn(s0, s1);
            }
        }
}

// ---------------- GEMM B: out = h @ w2 ----------------
__global__ __launch_bounds__(256, 2)
void gB(const float* __restrict__ w2, float* __restrict__ out)
{
    __shared__ __half   Asm2[2][TILE_M * ASTR];  // 12288 B
    __shared__ uint32_t B2p [2][8 * BPSTR];      //  8704 B

    int tid = threadIdx.x, lane = tid & 31, wid = tid >> 5;
    int wm = wid & 1, wn = wid >> 1;
    int g = lane >> 2, qi = lane & 3;
    int rt = blockIdx.x, ct = blockIdx.y;        // rt-fastest (R9 orientation)
    int rowstart = rt * TILE_M;
    if (rowstart >= g_off[NE]) return;
    int e = 0;
    while (e < NE - 1 && rowstart >= g_off[e + 1]) e++;
    int n0 = ct * 128;

    const __half* Ab  = g_h + (size_t)rowstart * NF;
    const float*  w2e = w2 + (size_t)e * NF * NH + n0;

    float acc[4][4][4];
#pragma unroll
    for (int i = 0; i < 4; i++)
#pragma unroll
        for (int j = 0; j < 4; j++)
#pragma unroll
            for (int q = 0; q < 4; q++) acc[i][j][q] = 0.f;

    uint4  pa;
    float4 pb0, pb1;
    const int aro = tid >> 1, aqo = (tid & 1) * 8;
    const int bkp = tid >> 5, bc4 = lane * 4;

    auto LDGr = [&](int kt) {
        int k0 = kt * 16;
        pa  = *(const uint4*) (Ab  + (size_t)aro * NF + k0 + aqo);
        pb0 = *(const float4*)(w2e + (size_t)(k0 + 2 * bkp)     * NH + bc4);
        pb1 = *(const float4*)(w2e + (size_t)(k0 + 2 * bkp + 1) * NH + bc4);
    };
    auto STSb = [&](int buf) {
        *(uint4*)&Asm2[buf][aro * ASTR + aqo] = pa;
        uint4 q = make_uint4(pack2f(pb0.x, pb1.x), pack2f(pb0.y, pb1.y),
                             pack2f(pb0.z, pb1.z), pack2f(pb0.w, pb1.w));
        *(uint4*)&B2p[buf][bkp * BPSTR + bc4] = q;
    };

    LDGr(0); STSb(0); __syncthreads();
    const int KT = NF / 16;   // 256
    for (int kt = 0; kt < KT; kt++) {
        if (kt + 1 < KT) LDGr(kt + 1);
        int buf = kt & 1;
        uint32_t a[4][4];
#pragma unroll
        for (int mt = 0; mt < 4; mt++) {
            int r = wm * 64 + mt * 16 + g;
            a[mt][0] = *(const uint32_t*)&Asm2[buf][ r      * ASTR + 2 * qi];
            a[mt][1] = *(const uint32_t*)&Asm2[buf][(r + 8) * ASTR + 2 * qi];
            a[mt][2] = *(const uint32_t*)&Asm2[buf][ r      * ASTR + 8 + 2 * qi];
            a[mt][3] = *(const uint32_t*)&Asm2[buf][(r + 8) * ASTR + 8 + 2 * qi];
        }
#pragma unroll
        for (int nn = 0; nn < 4; nn++) {
            int col = wn * 32 + nn * 8 + g;
            uint32_t b[2];
            b[0] = B2p[buf][ qi      * BPSTR + col];
            b[1] = B2p[buf][(qi + 4) * BPSTR + col];
#pragma unroll
            for (int mt = 0; mt < 4; mt++) MMA(acc[mt][nn], a[mt], b);
        }
        if (kt + 1 < KT) { STSb(buf ^ 1); __syncthreads(); }
    }

    int colbase = n0 + wn * 32 + qi * 2;
#pragma unroll
    for (int mt = 0; mt < 4; mt++)
#pragma unroll
        for (int rs = 0; rs < 2; rs++) {
            int lrow = wm * 64 + mt * 16 + g + rs * 8;
            int f = g_row_ids[rowstart + lrow];
            if (f < 0) continue;
            float* dst = out + (size_t)f * NH + colbase;
#pragma unroll
            for (int nn = 0; nn < 4; nn++) {
                float2 v = make_float2(acc[mt][nn][rs * 2], acc[mt][nn][rs * 2 + 1]);
                *(float2*)(dst + nn * 8) = v;
            }
        }
}

// ---------------- launch ----------------
extern "C" void kernel_launch(void* const* d_in, const int* in_sizes, int n_in,
                              void* d_out, int out_size)
{
    const float* x     = (const float*)d_in[0];
    const int*   topks = (const int*)  d_in[1];
    const float* w1    = (const float*)d_in[2];
    const float* w2    = (const float*)d_in[3];
    const float* w3    = (const float*)d_in[4];
    float* out = (float*)d_out;

    k_zero      <<<1, 32>>>();
    k_count_fill<<<256, 256>>>(topks);
    k_offsets   <<<1, 1>>>();
    k_scatter   <<<256, 256>>>(topks);
    gA<<<dim3(MAX_TILES, 32), 256>>>(x, w1, w3);
    gB<<<dim3(MAX_TILES, 16), 256>>>(w2, out);
}

// round 16
// speedup vs baseline: 1.3114x; 1.0162x over previous
#include <cuda_runtime.h>
#include <cuda_fp16.h>
#include <stdint.h>
#include <math.h>

// ---------------- problem constants ----------------
#define MM      32768
#define TOPK    2
#define NH      2048
#define NF      4096
#define NE      8
#define NA      (MM*TOPK)
#define TILE_M  128
#define MAX_TILES 521
#define CAP     (MAX_TILES*TILE_M)     // 66688 padded rows

// ---------------- device scratch (proven footprint) ----------------
__device__ int    g_counts[NE];
__device__ int    g_cursor[NE];
__device__ int    g_off[NE+1];
__device__ int    g_row_ids[CAP];
__device__ __align__(16) __half g_h[(size_t)CAP * (size_t)NF];   // fp16 intermediate

// ---------------- PTX helpers (sm_75+ only; plain sm_103-safe) ----------------
__device__ __forceinline__ uint32_t smem_u32(const void* p) {
    uint32_t a;
    asm("{ .reg .u64 t; cvta.to.shared.u64 t, %1; cvt.u32.u64 %0, t; }" : "=r"(a) : "l"(p));
    return a;
}
#define MMA(c,a,b) \
    asm volatile("mma.sync.aligned.m16n8k16.row.col.f32.f16.f16.f32 " \
        "{%0,%1,%2,%3}, {%4,%5,%6,%7}, {%8,%9}, {%0,%1,%2,%3};" \
        : "+f"((c)[0]),"+f"((c)[1]),"+f"((c)[2]),"+f"((c)[3]) \
        : "r"((a)[0]),"r"((a)[1]),"r"((a)[2]),"r"((a)[3]),"r"((b)[0]),"r"((b)[1]))
#define LDMX4(r0,r1,r2,r3,addr) \
    asm volatile("ldmatrix.sync.aligned.m8n8.x4.shared.b16 {%0,%1,%2,%3}, [%4];" \
        : "=r"(r0),"=r"(r1),"=r"(r2),"=r"(r3) : "r"(addr))
#define LDMX2T(r0,r1,addr) \
    asm volatile("ldmatrix.sync.aligned.m8n8.x2.trans.shared.b16 {%0,%1}, [%2];" \
        : "=r"(r0),"=r"(r1) : "r"(addr))

// A smem: [m=128][k=16] halfs, row stride ASTR=24 halfs (48B).
// ldmatrix rows: 12*l mod 32 words = {0,12,24,4,16,28,8,20}: conflict-free.
#define ASTR 24
#define ASZB (TILE_M * ASTR * 2)       // 6144 B per buffer
// B smem: [k=16][n=128] halfs, row stride BSTR=136 halfs (272B).
// ldmatrix.trans k-rows: 68k mod 32 words = 4k pattern: conflict-free.
#define BSTR 136
#define BSZB (16 * BSTR * 2)           // 4352 B per buffer

// ---------------- setup kernels (verbatim, proven) ----------------
__global__ void k_zero() {
    int t = threadIdx.x;
    if (t < NE) { g_counts[t] = 0; g_cursor[t] = 0; }
}
__global__ void k_count_fill(const int* __restrict__ topks) {
    __shared__ int h[NE];
    int t = threadIdx.x;
    if (t < NE) h[t] = 0;
    __syncthreads();
    int stride = gridDim.x * blockDim.x;
    int i = blockIdx.x * blockDim.x + t;
    for (int p = i; p < CAP; p += stride) g_row_ids[p] = -1;
    for (int p = i; p < NA; p += stride) atomicAdd(&h[topks[p]], 1);
    __syncthreads();
    if (t < NE && h[t]) atomicAdd(&g_counts[t], h[t]);
}
__global__ void k_offsets() {
    int s = 0; g_off[0] = 0;
    for (int e = 0; e < NE; e++) {
        s += (g_counts[e] + (TILE_M - 1)) & ~(TILE_M - 1);
        g_off[e + 1] = s;
    }
}
__global__ void k_scatter(const int* __restrict__ topks) {
    int stride = gridDim.x * blockDim.x;
    int i = blockIdx.x * blockDim.x + threadIdx.x;
    for (int p = i; p < NA; p += stride) {
        int e = topks[p];
        int pos = g_off[e] + atomicAdd(&g_cursor[e], 1);
        g_row_ids[pos] = p;
    }
}

// ---------------- GEMM A: h = silu(x@w1) * (x@w3) ----------------
// CTA 128M x 128N, K-step 16. Grid (rt=521, ct=32) rt-fastest (proven).
__global__ __launch_bounds__(256, 1)
void gA(const float* __restrict__ x,
        const float* __restrict__ w1,
        const float* __restrict__ w3)
{
    __shared__ __half Asm[2][TILE_M * ASTR];   // 12288 B
    __shared__ __half B1s[2][16 * BSTR];       //  8704 B
    __shared__ __half B3s[2][16 * BSTR];       //  8704 B
    __shared__ int    tok[TILE_M];

    int tid = threadIdx.x, lane = tid & 31, wid = tid >> 5;
    int wm = wid & 1, wn = wid >> 1;
    int g = lane >> 2, qi = lane & 3;
    int rt = blockIdx.x, ct = blockIdx.y;
    int rowstart = rt * TILE_M;
    if (rowstart >= g_off[NE]) return;
    int e = 0;
    while (e < NE - 1 && rowstart >= g_off[e + 1]) e++;
    int n0 = ct * 128;

    if (tid < TILE_M) {
        int f = g_row_ids[rowstart + tid];
        tok[tid] = (f < 0) ? 0 : (f >> 1);
    }
    __syncthreads();

    const float* w1e = w1 + (size_t)e * NH * NF + n0;
    const float* w3e = w3 + (size_t)e * NH * NF + n0;

    float accg[4][4][4], accu[4][4][4];
#pragma unroll
    for (int i = 0; i < 4; i++)
#pragma unroll
        for (int j = 0; j < 4; j++)
#pragma unroll
            for (int q = 0; q < 4; q++) { accg[i][j][q] = 0.f; accu[i][j][q] = 0.f; }

    float4 pa0, pa1, p10, p11, p30, p31;
    const int ar0 = tid >> 2,         ak0 = (tid & 3) * 4;
    const int ar1 = (tid + 256) >> 2, ak1 = ((tid + 256) & 3) * 4;
    const int bkp = tid >> 5;                 // k-pair row 0..7
    const int bc4 = lane * 4;                 // col group

    auto LDGr = [&](int kt) {
        int k0 = kt * 16;
        pa0 = *(const float4*)(x + (size_t)tok[ar0] * NH + k0 + ak0);
        pa1 = *(const float4*)(x + (size_t)tok[ar1] * NH + k0 + ak1);
        p10 = *(const float4*)(w1e + (size_t)(k0 + 2 * bkp)     * NF + bc4);
        p11 = *(const float4*)(w1e + (size_t)(k0 + 2 * bkp + 1) * NF + bc4);
        p30 = *(const float4*)(w3e + (size_t)(k0 + 2 * bkp)     * NF + bc4);
        p31 = *(const float4*)(w3e + (size_t)(k0 + 2 * bkp + 1) * NF + bc4);
    };
    auto cvt2 = [&](float4 v) {
        __half2 h0 = __floats2half2_rn(v.x, v.y);
        __half2 h1 = __floats2half2_rn(v.z, v.w);
        return make_uint2(*(uint32_t*)&h0, *(uint32_t*)&h1);
    };
    auto STSb = [&](int buf) {
        *(uint2*)&Asm[buf][ar0 * ASTR + ak0] = cvt2(pa0);
        *(uint2*)&Asm[buf][ar1 * ASTR + ak1] = cvt2(pa1);
        *(uint2*)&B1s[buf][(2 * bkp)     * BSTR + bc4] = cvt2(p10);
        *(uint2*)&B1s[buf][(2 * bkp + 1) * BSTR + bc4] = cvt2(p11);
        *(uint2*)&B3s[buf][(2 * bkp)     * BSTR + bc4] = cvt2(p30);
        *(uint2*)&B3s[buf][(2 * bkp + 1) * BSTR + bc4] = cvt2(p31);
    };

    // ldmatrix lane addresses
    const uint32_t asb = smem_u32(&Asm[0][0]);
    const uint32_t b1b = smem_u32(&B1s[0][0]);
    const uint32_t b3b = smem_u32(&B3s[0][0]);
    const uint32_t aoff = ((uint32_t)((wm * 64 + (lane & 15)) * ASTR + (lane >> 4) * 8)) * 2;
    const uint32_t boff = ((uint32_t)((lane & 15) * BSTR + wn * 32)) * 2;

    LDGr(0); STSb(0); __syncthreads();
    const int KT = NH / 16;   // 128
    for (int kt = 0; kt < KT; kt++) {
        if (kt + 1 < KT) LDGr(kt + 1);
        int buf = kt & 1;
        uint32_t a[4][4];
        uint32_t abase = asb + buf * ASZB + aoff;
#pragma unroll
        for (int mt = 0; mt < 4; mt++)
            LDMX4(a[mt][0], a[mt][1], a[mt][2], a[mt][3], abase + mt * 16 * ASTR * 2);
        uint32_t b1base = b1b + buf * BSZB + boff;
        uint32_t b3base = b3b + buf * BSZB + boff;
#pragma unroll
        for (int nn = 0; nn < 4; nn++) {
            uint32_t b1[2], b3[2];
            LDMX2T(b1[0], b1[1], b1base + nn * 16);
            LDMX2T(b3[0], b3[1], b3base + nn * 16);
#pragma unroll
            for (int mt = 0; mt < 4; mt++) {
                MMA(accg[mt][nn], a[mt], b1);
                MMA(accu[mt][nn], a[mt], b3);
            }
        }
        if (kt + 1 < KT) { STSb(buf ^ 1); __syncthreads(); }
    }

    // epilogue: silu(g)*u -> fp16 h
    int colbase = n0 + wn * 32 + qi * 2;
#pragma unroll
    for (int mt = 0; mt < 4; mt++)
#pragma unroll
        for (int rs = 0; rs < 2; rs++) {
            int row = rowstart + wm * 64 + mt * 16 + g + rs * 8;
            __half* dst = g_h + (size_t)row * NF + colbase;
#pragma unroll
            for (int nn = 0; nn < 4; nn++) {
                float g0 = accg[mt][nn][rs * 2],     u0 = accu[mt][nn][rs * 2];
                float g1 = accg[mt][nn][rs * 2 + 1], u1 = accu[mt][nn][rs * 2 + 1];
                float s0 = g0 / (1.f + __expf(-g0)) * u0;
                float s1 = g1 / (1.f + __expf(-g1)) * u1;
                *(__half2*)(dst + nn * 8) = __floats2half2_rn(s0, s1);
            }
        }
}

// ---------------- GEMM B: out = h @ w2 ----------------
__global__ __launch_bounds__(256, 2)
void gB(const float* __restrict__ w2, float* __restrict__ out)
{
    __shared__ __half Asm2[2][TILE_M * ASTR];  // 12288 B
    __shared__ __half B2s [2][16 * BSTR];      //  8704 B

    int tid = threadIdx.x, lane = tid & 31, wid = tid >> 5;
    int wm = wid & 1, wn = wid >> 1;
    int g = lane >> 2, qi = lane & 3;
    int rt = blockIdx.x, ct = blockIdx.y;
    int rowstart = rt * TILE_M;
    if (rowstart >= g_off[NE]) return;
    int e = 0;
    while (e < NE - 1 && rowstart >= g_off[e + 1]) e++;
    int n0 = ct * 128;

    const __half* Ab  = g_h + (size_t)rowstart * NF;
    const float*  w2e = w2 + (size_t)e * NF * NH + n0;

    float acc[4][4][4];
#pragma unroll
    for (int i = 0; i < 4; i++)
#pragma unroll
        for (int j = 0; j < 4; j++)
#pragma unroll
            for (int q = 0; q < 4; q++) acc[i][j][q] = 0.f;

    uint4  pa;
    float4 pb0, pb1;
    const int aro = tid >> 1, aqo = (tid & 1) * 8;
    const int bkp = tid >> 5, bc4 = lane * 4;

    auto LDGr = [&](int kt) {
        int k0 = kt * 16;
        pa  = *(const uint4*) (Ab  + (size_t)aro * NF + k0 + aqo);
        pb0 = *(const float4*)(w2e + (size_t)(k0 + 2 * bkp)     * NH + bc4);
        pb1 = *(const float4*)(w2e + (size_t)(k0 + 2 * bkp + 1) * NH + bc4);
    };
    auto cvt2 = [&](float4 v) {
        __half2 h0 = __floats2half2_rn(v.x, v.y);
        __half2 h1 = __floats2half2_rn(v.z, v.w);
        return make_uint2(*(uint32_t*)&h0, *(uint32_t*)&h1);
    };
    auto STSb = [&](int buf) {
        *(uint4*)&Asm2[buf][aro * ASTR + aqo] = pa;
        *(uint2*)&B2s[buf][(2 * bkp)     * BSTR + bc4] = cvt2(pb0);
        *(uint2*)&B2s[buf][(2 * bkp + 1) * BSTR + bc4] = cvt2(pb1);
    };

    const uint32_t asb = smem_u32(&Asm2[0][0]);
    const uint32_t b2b = smem_u32(&B2s[0][0]);
    const uint32_t aoff = ((uint32_t)((wm * 64 + (lane & 15)) * ASTR + (lane >> 4) * 8)) * 2;
    const uint32_t boff = ((uint32_t)((lane & 15) * BSTR + wn * 32)) * 2;

    LDGr(0); STSb(0); __syncthreads();
    const int KT = NF / 16;   // 256
    for (int kt = 0; kt < KT; kt++) {
        if (kt + 1 < KT) LDGr(kt + 1);
        int buf = kt & 1;
        uint32_t a[4][4];
        uint32_t abase = asb + buf * ASZB + aoff;
#pragma unroll
        for (int mt = 0; mt < 4; mt++)
            LDMX4(a[mt][0], a[mt][1], a[mt][2], a[mt][3], abase + mt * 16 * ASTR * 2);
        uint32_t bbase = b2b + buf * BSZB + boff;
#pragma unroll
        for (int nn = 0; nn < 4; nn++) {
            uint32_t b[2];
            LDMX2T(b[0], b[1], bbase + nn * 16);
#pragma unroll
            for (int mt = 0; mt < 4; mt++) MMA(acc[mt][nn], a[mt], b);
        }
        if (kt + 1 < KT) { STSb(buf ^ 1); __syncthreads(); }
    }

    int colbase = n0 + wn * 32 + qi * 2;
#pragma unroll
    for (int mt = 0; mt < 4; mt++)
#pragma unroll
        for (int rs = 0; rs < 2; rs++) {
            int lrow = wm * 64 + mt * 16 + g + rs * 8;
            int f = g_row_ids[rowstart + lrow];
            if (f < 0) continue;
            float* dst = out + (size_t)f * NH + colbase;
#pragma unroll
            for (int nn = 0; nn < 4; nn++) {
                float2 v = make_float2(acc[mt][nn][rs * 2], acc[mt][nn][rs * 2 + 1]);
                *(float2*)(dst + nn * 8) = v;
            }
        }
}

// ---------------- launch ----------------
extern "C" void kernel_launch(void* const* d_in, const int* in_sizes, int n_in,
                              void* d_out, int out_size)
{
    const float* x     = (const float*)d_in[0];
    const int*   topks = (const int*)  d_in[1];
    const float* w1    = (const float*)d_in[2];
    const float* w2    = (const float*)d_in[3];
    const float* w3    = (const float*)d_in[4];
    float* out = (float*)d_out;

    k_zero      <<<1, 32>>>();
    k_count_fill<<<256, 256>>>(topks);
    k_offsets   <<<1, 1>>>();
    k_scatter   <<<256, 256>>>(topks);
    gA<<<dim3(MAX_TILES, 32), 256>>>(x, w1, w3);
    gB<<<dim3(MAX_TILES, 16), 256>>>(w2, out);
}